// round 13
// baseline (speedup 1.0000x reference)
#include <cuda_runtime.h>
#include <cstdint>

#define Bn    8
#define Nn    8192
#define Cn    91
#define CAPc  163840          // >= max kept candidates per image
#define NB    9216            // histogram bins over score float bits >> 12
#define BASE_BIN 251084       // bits(0.05f) >> 12
#define SEL_CAP 2048
#define NCHUNK 64
#define TPB   1024
#define DETS  100
#define CLIPV 4.135166556742356f   // log(1000/16)
#define FULLM 0xffffffffu

// ------------------------------------------------------------------
// static device scratch (zero-initialized at load; k_nms restores the
// zeros it consumed -> graph-replay deterministic)
// ------------------------------------------------------------------
__device__ unsigned long long g_keys[Bn][CAPc];
__device__ int                g_cnt [Bn];

__device__ __forceinline__ void stf(float* o, int i, float v, int n) {
    if (i < n) o[i] = v;
}

// reference-rounding IoU on offset coordinates; returns (iou > 0.5)
__device__ __forceinline__ bool iou_sup(float4 A, float4 Bx, float off) {
    float ax1 = A.x + off, ay1 = A.y + off, ax2 = A.z + off, ay2 = A.w + off;
    float bx1 = Bx.x + off, by1 = Bx.y + off, bx2 = Bx.z + off, by2 = Bx.w + off;
    float ltx = fmaxf(ax1, bx1), lty = fmaxf(ay1, by1);
    float rbx = fminf(ax2, bx2), rby = fminf(ay2, by2);
    float ww = fmaxf(rbx - ltx, 0.f), hh = fmaxf(rby - lty, 0.f);
    float inter = ww * hh;
    float a1 = (ax2 - ax1) * (ay2 - ay1);
    float a2 = (bx2 - bx1) * (by2 - by1);
    float iou = __fdiv_rn(inter, a1 + a2 - inter + 1e-9f);
    return iou > 0.5f;
}

// byte-identical box decode for candidate (g, c)
__device__ __forceinline__ float4 decode_box(const float* __restrict__ reg,
                                             const float* __restrict__ props,
                                             int g, int c) {
    float4 p = reinterpret_cast<const float4*>(props)[g];
    float w  = p.z - p.x;
    float h  = p.w - p.y;
    float cx = p.x + 0.5f * w;
    float cy = p.y + 0.5f * h;
    const float4* Q = reinterpret_cast<const float4*>(reg + (size_t)g * (Cn * 4));
    float4 q = Q[c];
    float dx = __fdiv_rn(q.x, 10.0f);
    float dy = __fdiv_rn(q.y, 10.0f);
    float dw = fminf(__fdiv_rn(q.z, 5.0f), CLIPV);
    float dh = fminf(__fdiv_rn(q.w, 5.0f), CLIPV);
    float pcx = dx * w + cx;
    float pcy = dy * h + cy;
    float pw  = expf(dw) * w;
    float ph  = expf(dh) * h;
    float x1 = fminf(fmaxf(pcx - 0.5f * pw, 0.f), 800.f);
    float y1 = fminf(fmaxf(pcy - 0.5f * ph, 0.f), 800.f);
    float x2 = fminf(fmaxf(pcx + 0.5f * pw, 0.f), 800.f);
    float y2 = fminf(fmaxf(pcy + 0.5f * ph, 0.f), 800.f);
    return make_float4(x1, y1, x2, y2);
}

// decode + filter + key emit for one proposal's survivors (warp-wide)
__device__ __forceinline__ void emit_prop(int g, int n, int lane,
                                          unsigned mA, unsigned mB, unsigned mC,
                                          float e0, float e1, float e2, float s,
                                          const float* __restrict__ reg,
                                          const float* __restrict__ props,
                                          bool& ok, float& sc, int& c) {
    int c0  = __popc(mA);
    int c01 = c0 + __popc(mB);
    int tot = c01 + __popc(mC);
    ok = false; sc = 0.f; c = 0;
    if (tot == 0) return;

    int src = 0, k = 0;
    if (lane < c0)       { k = 0; src = __fns(mA, 0, lane + 1); }
    else if (lane < c01) { k = 1; src = __fns(mB, 0, lane - c0 + 1); }
    else if (lane < tot) { k = 2; src = __fns(mC, 0, lane - c01 + 1); }
    src &= 31;
    float eA = __shfl_sync(FULLM, e0, src);
    float eB = __shfl_sync(FULLM, e1, src);
    float eC = __shfl_sync(FULLM, e2, src);
    float e  = (k == 2) ? eC : ((k == 1) ? eB : eA);
    c = src + (k << 5);

    ok = (lane < tot);
    sc = __fdiv_rn(e, s);                 // exact softmax value
    ok = ok && (sc > 0.05f);
    if (ok) {
        float4 bx = decode_box(reg, props, g, c);
        ok = ((bx.z - bx.x) >= 1.0f) && ((bx.w - bx.y) >= 1.0f);
    }
}

// ------------------------------------------------------------------
// K1: two proposals per warp, interleaved chains
// ------------------------------------------------------------------
__global__ __launch_bounds__(256) void k_cand(const float* __restrict__ logits,
                                              const float* __restrict__ reg,
                                              const float* __restrict__ props) {
    int warp = threadIdx.x >> 5;
    int lane = threadIdx.x & 31;
    int gA = blockIdx.x * 16 + warp * 2;      // even
    int gB = gA + 1;                          // same image
    int b  = gA >> 13;
    int nA = gA & (Nn - 1);
    int nB = gB & (Nn - 1);

    const float* LA = logits + (size_t)gA * Cn;
    const float* LB = logits + (size_t)gB * Cn;
    float a0 = LA[lane];
    float b0 = LB[lane];
    float a1 = (lane + 32 < Cn) ? LA[lane + 32] : -1e30f;
    float b1 = (lane + 32 < Cn) ? LB[lane + 32] : -1e30f;
    float a2 = (lane + 64 < Cn) ? LA[lane + 64] : -1e30f;
    float b2 = (lane + 64 < Cn) ? LB[lane + 64] : -1e30f;

    float mxa = fmaxf(a0, fmaxf(a1, a2));
    float mxb = fmaxf(b0, fmaxf(b1, b2));
    #pragma unroll
    for (int o = 16; o; o >>= 1) {
        mxa = fmaxf(mxa, __shfl_xor_sync(FULLM, mxa, o));
        mxb = fmaxf(mxb, __shfl_xor_sync(FULLM, mxb, o));
    }

    float ea0 = expf(a0 - mxa);
    float eb0 = expf(b0 - mxb);
    float ea1 = (lane + 32 < Cn) ? expf(a1 - mxa) : 0.0f;
    float eb1 = (lane + 32 < Cn) ? expf(b1 - mxb) : 0.0f;
    float ea2 = (lane + 64 < Cn) ? expf(a2 - mxa) : 0.0f;
    float eb2 = (lane + 64 < Cn) ? expf(b2 - mxb) : 0.0f;
    float sa = ea0 + ea1 + ea2;
    float sb = eb0 + eb1 + eb2;
    #pragma unroll
    for (int o = 16; o; o >>= 1) {
        sa += __shfl_xor_sync(FULLM, sa, o);
        sb += __shfl_xor_sync(FULLM, sb, o);
    }

    float pta = 0.0497f * sa;
    float ptb = 0.0497f * sb;
    bool okA0 = (lane >= 1) && (ea0 > pta);
    bool okA1 = (ea1 > pta);
    bool okA2 = (ea2 > pta);
    bool okB0 = (lane >= 1) && (eb0 > ptb);
    bool okB1 = (eb1 > ptb);
    bool okB2 = (eb2 > ptb);

    unsigned mAa = __ballot_sync(FULLM, okA0);
    unsigned mBa = __ballot_sync(FULLM, okA1);
    unsigned mCa = __ballot_sync(FULLM, okA2);
    unsigned mAb = __ballot_sync(FULLM, okB0);
    unsigned mBb = __ballot_sync(FULLM, okB1);
    unsigned mCb = __ballot_sync(FULLM, okB2);
    if ((mAa | mBa | mCa | mAb | mBb | mCb) == 0u) return;   // warp-uniform

    bool okA, okB; float scA, scB; int cA, cB;
    emit_prop(gA, nA, lane, mAa, mBa, mCa, ea0, ea1, ea2, sa, reg, props, okA, scA, cA);
    emit_prop(gB, nB, lane, mAb, mBb, mCb, eb0, eb1, eb2, sb, reg, props, okB, scB, cB);

    unsigned fmA = __ballot_sync(FULLM, okA);
    unsigned fmB = __ballot_sync(FULLM, okB);
    int cntA = __popc(fmA);
    int tot = cntA + __popc(fmB);
    if (tot) {
        int base = 0;
        if (lane == 0) base = atomicAdd(&g_cnt[b], tot);
        base = __shfl_sync(FULLM, base, 0);
        unsigned below = (1u << lane) - 1u;
        if (okA) {
            int pos = base + __popc(fmA & below);
            if (pos < CAPc) {
                unsigned m = (unsigned)(nA * 90 + (cA - 1));
                unsigned sbb = __float_as_uint(scA);
                g_keys[b][pos] = ((unsigned long long)sbb << 32) | (0xFFFFFFFFu - m);
            }
        }
        if (okB) {
            int pos = base + cntA + __popc(fmB & below);
            if (pos < CAPc) {
                unsigned m = (unsigned)(nB * 90 + (cB - 1));
                unsigned sbb = __float_as_uint(scB);
                g_keys[b][pos] = ((unsigned long long)sbb << 32) | (0xFFFFFFFFu - m);
            }
        }
    }
}

// ------------------------------------------------------------------
// warp-level descending bitonic sort, 32*R elements (e = lane + 32*r)
// ------------------------------------------------------------------
__device__ __forceinline__ void cswap(unsigned long long& a, unsigned long long& b,
                                      bool desc) {
    unsigned long long mx = (a > b) ? a : b;
    unsigned long long mn = (a > b) ? b : a;
    a = desc ? mx : mn;
    b = desc ? mn : mx;
}

template <int R>
__device__ void warp_sort_desc(unsigned long long* v, int lane) {
    const int N = 32 * R;
    #pragma unroll
    for (int k2 = 2; k2 <= N; k2 <<= 1) {
        #pragma unroll
        for (int j = N >> 1; j > 0; j >>= 1) {
            if (j >= k2) continue;       // (unrolled-friendly stage filter)
            if (j >= 32) {
                int rj = j >> 5;
                #pragma unroll
                for (int r = 0; r < R; r++) {
                    int r2 = r ^ rj;
                    if (r2 > r) {
                        int e = lane + 32 * r;
                        cswap(v[r], v[r2], (e & k2) == 0);
                    }
                }
            } else {
                #pragma unroll
                for (int r = 0; r < R; r++) {
                    unsigned long long p = __shfl_xor_sync(FULLM, v[r], j);
                    int e = lane + 32 * r;
                    bool desc  = ((e & k2) == 0);
                    bool lower = ((lane & j) == 0);
                    bool pg    = (p > v[r]);
                    if ((desc == lower) == pg) v[r] = p;
                }
            }
        }
    }
}

// ------------------------------------------------------------------
// K2 shared memory
// ------------------------------------------------------------------
struct SM {
    float4 cls_box[SEL_CAP];            // boxes of class-sorted candidates 32768
    float4 cls_acc[32][DETS];           // per-warp class accepted scratch  51200
    float4 abox[DETS];                  // global accepted boxes             1600
    unsigned long long skey[SEL_CAP];   // scan buffer, later survivors     16384
    unsigned long long cls_key[SEL_CAP];// class-partitioned sorted keys    16384
    int    sfx[NB];                     //                                  36864
    unsigned short chunkcnt[NCHUNK][128]; //                                16384
    int    cls_cnt[128];
    int    cls_off[96];
    int    albl[DETS];
    int    wtot[32], wexc[32];
    int    s_cnt, s_acc, s_scnt;
};

__global__ __launch_bounds__(TPB) void k_nms(const float* __restrict__ reg,
                                             const float* __restrict__ props,
                                             float* __restrict__ out, int out_size) {
    extern __shared__ __align__(16) char smraw[];
    SM* sm = reinterpret_cast<SM*>(smraw);
    int b = blockIdx.x;
    int t = threadIdx.x;
    int lane = t & 31;
    int warp = t >> 5;
    unsigned below = (1u << lane) - 1u;

    int Ktot = min(g_cnt[b], CAPc);

    // ---- build histogram in smem from keys (MLP-8 batched) ----
    const int PER = NB / TPB;   // 9
    int lo = t * PER;
    #pragma unroll
    for (int i = 0; i < PER; i++) sm->sfx[lo + i] = 0;
    __syncthreads();
    for (int i0 = 0; i0 < Ktot; i0 += TPB * 8) {
        unsigned long long kv[8];
        #pragma unroll
        for (int k = 0; k < 8; k++) {
            int i = i0 + k * TPB + t;
            kv[k] = (i < Ktot) ? g_keys[b][i] : 0ULL;
        }
        #pragma unroll
        for (int k = 0; k < 8; k++) {
            if (kv[k]) {
                int bin = (int)((unsigned)(kv[k] >> 32) >> 12) - BASE_BIN;
                bin = max(0, min(bin, NB - 1));
                atomicAdd(&sm->sfx[bin], 1);
            }
        }
    }
    __syncthreads();

    // ---- hierarchical suffix sums in place ----
    int cnts[PER];
    #pragma unroll
    for (int i = 0; i < PER; i++) cnts[i] = sm->sfx[lo + i];
    int ls = 0;
    #pragma unroll
    for (int i = 0; i < PER; i++) ls += cnts[i];
    int v = ls;
    #pragma unroll
    for (int off = 1; off < 32; off <<= 1) {
        int u = __shfl_down_sync(FULLM, v, off);
        if (lane + off < 32) v += u;
    }
    if (lane == 0) sm->wtot[warp] = v;
    __syncthreads();
    if (t < 32) {
        int x = sm->wtot[t];
        int vv = x;
        #pragma unroll
        for (int off = 1; off < 32; off <<= 1) {
            int u = __shfl_down_sync(FULLM, vv, off);
            if (t + off < 32) vv += u;
        }
        sm->wexc[t] = vv - x;
    }
    if (t == 0) sm->s_acc = 0;
    __syncthreads();
    int run = sm->wexc[warp] + (v - ls);
    for (int i = PER - 1; i >= 0; i--) {
        run += cnts[i];
        sm->sfx[lo + i] = run;
    }
    __syncthreads();

    int b_hi = NB;

    while (sm->s_acc < DETS) {
        int top = (b_hi < NB) ? sm->sfx[b_hi] : 0;
        if (b_hi == 0 || sm->sfx[0] - top == 0) break;

        // smallest wlo with sfx[wlo] - top <= SEL_CAP
        int sl = 0, sh = b_hi;
        while (sl < sh) {
            int mid = (sl + sh) >> 1;
            if (sm->sfx[mid] - top <= SEL_CAP) sh = mid; else sl = mid + 1;
        }
        int wlo = sl;
        if (wlo >= b_hi) wlo = b_hi - 1;
        int whi = b_hi;
        b_hi = wlo;

        if (t == 0) { sm->s_cnt = 0; sm->s_scnt = 0; }
        __syncthreads();
        // ---- MLP-8 selection scan into skey ----
        for (int i0 = 0; i0 < Ktot; i0 += TPB * 8) {
            unsigned long long kv[8];
            #pragma unroll
            for (int k = 0; k < 8; k++) {
                int i = i0 + k * TPB + t;
                kv[k] = (i < Ktot) ? g_keys[b][i] : 0ULL;
            }
            #pragma unroll
            for (int k = 0; k < 8; k++) {
                if (kv[k]) {
                    int bin = (int)((unsigned)(kv[k] >> 32) >> 12) - BASE_BIN;
                    bin = max(0, min(bin, NB - 1));
                    if (bin >= wlo && bin < whi) {
                        int pos = atomicAdd(&sm->s_cnt, 1);
                        if (pos < SEL_CAP) sm->skey[pos] = kv[k];
                    }
                }
            }
        }
        __syncthreads();
        int nsel = min(sm->s_cnt, SEL_CAP);
        if (nsel == 0) continue;

        // ---- zero chunk counters (viewed as u32) ----
        {
            unsigned* cc = reinterpret_cast<unsigned*>(&sm->chunkcnt[0][0]);
            #pragma unroll
            for (int i = 0; i < (NCHUNK * 128 / 2) / TPB; i++) cc[i * TPB + t] = 0;
        }
        __syncthreads();

        // ---- per-chunk class ranks: elements e=t (chunk=warp), e=t+1024 ----
        unsigned long long kA = (t < nsel) ? sm->skey[t] : 0ULL;
        unsigned long long kB = (t + 1024 < nsel) ? sm->skey[t + 1024] : 0ULL;
        int lblA = (t < nsel) ? (1 + (int)((0xFFFFFFFFu - (unsigned)kA) % 90u)) : (96 + lane);
        int lblB = (t + 1024 < nsel) ? (1 + (int)((0xFFFFFFFFu - (unsigned)kB) % 90u)) : (96 + lane);
        unsigned pA = __match_any_sync(FULLM, lblA);
        int rkA = __popc(pA & below);
        if (lane == (__ffs(pA) - 1)) sm->chunkcnt[warp][lblA] = (unsigned short)__popc(pA);
        unsigned pB = __match_any_sync(FULLM, lblB);
        int rkB = __popc(pB & below);
        if (lane == (__ffs(pB) - 1)) sm->chunkcnt[warp + 32][lblB] = (unsigned short)__popc(pB);
        __syncthreads();

        // ---- per-class prefix over chunks -> bases; totals in cls_cnt ----
        if (t < 128) {
            int run2 = 0;
            #pragma unroll 1
            for (int w = 0; w < NCHUNK; w++) {
                int tmp = sm->chunkcnt[w][t];
                sm->chunkcnt[w][t] = (unsigned short)run2;
                run2 += tmp;
            }
            sm->cls_cnt[t] = run2;
        }
        __syncthreads();

        // ---- exclusive offsets over classes 0..95 ----
        if (t < 32) {
            int c0i = t * 3;
            int s0 = sm->cls_cnt[c0i], s1 = sm->cls_cnt[c0i + 1], s2 = sm->cls_cnt[c0i + 2];
            int tt = s0 + s1 + s2;
            int rn = tt;
            #pragma unroll
            for (int off = 1; off < 32; off <<= 1) {
                int u = __shfl_up_sync(FULLM, rn, off);
                if (lane >= off) rn += u;
            }
            int ex = rn - tt;
            sm->cls_off[c0i] = ex;
            sm->cls_off[c0i + 1] = ex + s0;
            sm->cls_off[c0i + 2] = ex + s0 + s1;
        }
        __syncthreads();

        // ---- scatter keys into per-class segments ----
        if (t < nsel)
            sm->cls_key[sm->cls_off[lblA] + (int)sm->chunkcnt[warp][lblA] + rkA] = kA;
        if (t + 1024 < nsel)
            sm->cls_key[sm->cls_off[lblB] + (int)sm->chunkcnt[warp + 32][lblB] + rkB] = kB;
        int acc0 = sm->s_acc;
        int quota = DETS - acc0;
        __syncthreads();

        // ---- per-warp class sorts (descending, within-class score order) --
        #pragma unroll 1
        for (int jc = 0; jc < 3; jc++) {
            int c = warp + 1 + 32 * jc;
            if (c > 90) continue;
            int cnt = sm->cls_cnt[c];
            if (cnt <= 1) continue;
            int off = sm->cls_off[c];
            if (cnt <= 32) {
                unsigned long long vv[1];
                vv[0] = (lane < cnt) ? sm->cls_key[off + lane] : 0ULL;
                warp_sort_desc<1>(vv, lane);
                if (lane < cnt) sm->cls_key[off + lane] = vv[0];
            } else if (cnt <= 64) {
                unsigned long long vv[2];
                #pragma unroll
                for (int r = 0; r < 2; r++) {
                    int e = lane + 32 * r;
                    vv[r] = (e < cnt) ? sm->cls_key[off + e] : 0ULL;
                }
                warp_sort_desc<2>(vv, lane);
                #pragma unroll
                for (int r = 0; r < 2; r++) {
                    int e = lane + 32 * r;
                    if (e < cnt) sm->cls_key[off + e] = vv[r];
                }
            } else if (cnt <= 128) {
                unsigned long long vv[4];
                #pragma unroll
                for (int r = 0; r < 4; r++) {
                    int e = lane + 32 * r;
                    vv[r] = (e < cnt) ? sm->cls_key[off + e] : 0ULL;
                }
                warp_sort_desc<4>(vv, lane);
                #pragma unroll
                for (int r = 0; r < 4; r++) {
                    int e = lane + 32 * r;
                    if (e < cnt) sm->cls_key[off + e] = vv[r];
                }
            } else {
                // rare fallback: warp selection sort O(cnt^2/32)
                for (int i = 0; i < cnt - 1; i++) {
                    unsigned long long bk = 0ULL; int bi = i;
                    for (int j2 = i + lane; j2 < cnt; j2 += 32) {
                        unsigned long long kk = sm->cls_key[off + j2];
                        if (kk > bk) { bk = kk; bi = j2; }
                    }
                    #pragma unroll
                    for (int o = 16; o; o >>= 1) {
                        unsigned long long ok2 = __shfl_down_sync(FULLM, bk, o);
                        int oi = __shfl_down_sync(FULLM, bi, o);
                        if (ok2 > bk) { bk = ok2; bi = oi; }
                    }
                    bi = __shfl_sync(FULLM, bi, 0);
                    if (lane == 0 && bi != i) {
                        unsigned long long tmp = sm->cls_key[off + i];
                        sm->cls_key[off + i] = sm->cls_key[off + bi];
                        sm->cls_key[off + bi] = tmp;
                    }
                    __syncwarp();
                }
            }
            __syncwarp();
        }
        __syncthreads();

        // ---- decode boxes for all window candidates (class-sorted order) --
        #pragma unroll
        for (int half = 0; half < 2; half++) {
            int e = t + half * 1024;
            if (e < nsel) {
                unsigned m = 0xFFFFFFFFu - (unsigned)sm->cls_key[e];
                int n = (int)(m / 90u);
                int c = (int)(m % 90u) + 1;
                sm->cls_box[e] = decode_box(reg, props, b * Nn + n, c);
            }
        }
        __syncthreads();

        // ---- per-class greedy: warp w handles classes w+1, w+33, w+65 ----
        #pragma unroll 1
        for (int jc = 0; jc < 3; jc++) {
            int c = warp + 1 + 32 * jc;
            if (c > 90) continue;
            int cnt = sm->cls_cnt[c];
            if (cnt == 0) continue;
            int off = sm->cls_off[c];
            float offv = (float)c * 801.0f;

            int nacc = 0;
            for (int a0 = 0; a0 < acc0; a0 += 32) {
                int a = a0 + lane;
                bool mth = (a < acc0) && (sm->albl[a] == c);
                unsigned mm = __ballot_sync(FULLM, mth);
                if (mth) sm->cls_acc[warp][nacc + __popc(mm & below)] = sm->abox[a];
                nacc += __popc(mm);
            }

            int newacc = 0;
            for (int j = 0; j < cnt; j++) {
                float4 bx = sm->cls_box[off + j];
                bool sup = false;
                for (int a = lane; a < nacc; a += 32)
                    sup |= iou_sup(sm->cls_acc[warp][a], bx, offv);
                if (!__any_sync(FULLM, sup)) {
                    if (lane == 0) {
                        sm->cls_acc[warp][nacc] = bx;
                        int pos = atomicAdd(&sm->s_scnt, 1);
                        sm->skey[pos] = sm->cls_key[off + j];
                    }
                    nacc++;
                    newacc++;
                    if (newacc >= quota) break;
                }
            }
        }
        __syncthreads();

        int scnt = sm->s_scnt;
        if (scnt == 0) continue;

        // ---- zero-pad survivor buffer ----
        if (t >= scnt) sm->skey[t] = 0ULL;
        if (t + 1024 >= scnt && t + 1024 < SEL_CAP) sm->skey[t + 1024] = 0ULL;
        __syncthreads();

        int stored = min(scnt, quota);
        unsigned long long mykey = 0ULL;

        if (scnt <= 1024) {
            // ---- 1-reg block bitonic, runtime P ----
            int P = 32;
            while (P < scnt) P <<= 1;
            unsigned long long key = sm->skey[t];
            for (int k2 = 2; k2 <= P; k2 <<= 1) {
                for (int j = k2 >> 1; j > 0; j >>= 1) {
                    if (j >= 32) {
                        __syncthreads();
                        sm->skey[t] = key;
                        __syncthreads();
                        unsigned long long p = sm->skey[t ^ j];
                        bool desc = ((t & k2) == 0);
                        bool lowr = ((t & j) == 0);
                        if ((desc == lowr) == (p > key)) key = p;
                    } else {
                        unsigned long long p = __shfl_xor_sync(FULLM, key, j);
                        bool desc = ((t & k2) == 0);
                        bool lowr = ((lane & j) == 0);
                        if ((desc == lowr) == (p > key)) key = p;
                    }
                }
            }
            mykey = key;
        } else {
            // ---- 2-reg block bitonic, P = 2048 (rare) ----
            unsigned long long v0 = sm->skey[t];
            unsigned long long v1 = sm->skey[t + 1024];
            for (int k2 = 2; k2 <= 2048; k2 <<= 1) {
                for (int j = k2 >> 1; j > 0; j >>= 1) {
                    if (j == 1024) {
                        cswap(v0, v1, ((t & k2) == 0));
                    } else if (j >= 32) {
                        __syncthreads();
                        sm->skey[t] = v0;
                        sm->skey[t + 1024] = v1;
                        __syncthreads();
                        unsigned long long p0 = sm->skey[t ^ j];
                        unsigned long long p1 = sm->skey[(t + 1024) ^ j];
                        int e0 = t, e1 = t + 1024;
                        bool d0 = ((e0 & k2) == 0), l0 = ((e0 & j) == 0);
                        bool d1 = ((e1 & k2) == 0), l1 = ((e1 & j) == 0);
                        if ((d0 == l0) == (p0 > v0)) v0 = p0;
                        if ((d1 == l1) == (p1 > v1)) v1 = p1;
                    } else {
                        unsigned long long p0 = __shfl_xor_sync(FULLM, v0, j);
                        unsigned long long p1 = __shfl_xor_sync(FULLM, v1, j);
                        int e0 = t, e1 = t + 1024;
                        bool d0 = ((e0 & k2) == 0), l0 = ((lane & j) == 0);
                        bool d1 = ((e1 & k2) == 0);
                        if ((d0 == l0) == (p0 > v0)) v0 = p0;
                        if ((d1 == l0) == (p1 > v1)) v1 = p1;
                    }
                }
            }
            mykey = v0;   // element index t (< 1024 >= stored range)
        }

        // ---- output first `stored` survivors in descending key order ----
        if (t < stored) {
            unsigned m = 0xFFFFFFFFu - (unsigned)mykey;
            int n = (int)(m / 90u);
            int c = (int)(m % 90u) + 1;
            float4 bx = decode_box(reg, props, b * Nn + n, c);
            int slot = acc0 + t;
            sm->abox[slot] = bx;
            sm->albl[slot] = c;
            float sc = __uint_as_float((unsigned)(mykey >> 32));
            stf(out, b * (DETS * 4) + slot * 4 + 0, bx.x, out_size);
            stf(out, b * (DETS * 4) + slot * 4 + 1, bx.y, out_size);
            stf(out, b * (DETS * 4) + slot * 4 + 2, bx.z, out_size);
            stf(out, b * (DETS * 4) + slot * 4 + 3, bx.w, out_size);
            stf(out, Bn * DETS * 4 + b * DETS + slot, sc, out_size);
            stf(out, Bn * DETS * 5 + b * DETS + slot, (float)c, out_size);
            stf(out, Bn * DETS * 6 + b * DETS + slot, 1.0f, out_size);
        }
        __syncthreads();
        if (t == 0) sm->s_acc = acc0 + stored;
        __syncthreads();
    }

    // ---- zero-fill remaining detection slots ----
    __syncthreads();
    int accF = sm->s_acc;
    for (int a = accF + t; a < DETS; a += TPB) {
        stf(out, b * (DETS * 4) + a * 4 + 0, 0.f, out_size);
        stf(out, b * (DETS * 4) + a * 4 + 1, 0.f, out_size);
        stf(out, b * (DETS * 4) + a * 4 + 2, 0.f, out_size);
        stf(out, b * (DETS * 4) + a * 4 + 3, 0.f, out_size);
        stf(out, Bn * DETS * 4 + b * DETS + a, 0.f, out_size);
        stf(out, Bn * DETS * 5 + b * DETS + a, 0.f, out_size);
        stf(out, Bn * DETS * 6 + b * DETS + a, 0.f, out_size);
    }

    // ---- restore zeros for next graph replay ----
    if (t == 0) g_cnt[b] = 0;
}

// ------------------------------------------------------------------
// launcher
// ------------------------------------------------------------------
extern "C" void kernel_launch(void* const* d_in, const int* in_sizes, int n_in,
                              void* d_out, int out_size) {
    const float* logits = nullptr;
    const float* reg    = nullptr;
    const float* props  = nullptr;
    for (int i = 0; i < n_in; i++) {
        if      (in_sizes[i] == Bn * Nn * Cn)     logits = (const float*)d_in[i];
        else if (in_sizes[i] == Bn * Nn * Cn * 4) reg    = (const float*)d_in[i];
        else if (in_sizes[i] == Bn * Nn * 4)      props  = (const float*)d_in[i];
    }
    if (!logits && n_in > 0) logits = (const float*)d_in[0];
    if (!reg    && n_in > 1) reg    = (const float*)d_in[1];
    if (!props  && n_in > 2) props  = (const float*)d_in[2];

    cudaFuncSetAttribute(k_nms, cudaFuncAttributeMaxDynamicSharedMemorySize,
                         (int)sizeof(SM));

    k_cand<<<(Bn * Nn) / 16, 256>>>(logits, reg, props);
    k_nms<<<Bn, TPB, sizeof(SM)>>>(reg, props, (float*)d_out, out_size);
}

// round 14
// speedup vs baseline: 1.6552x; 1.6552x over previous
#include <cuda_runtime.h>
#include <cstdint>

#define Bn    8
#define Nn    8192
#define Cn    91
#define CAPc  163840          // >= max kept candidates per image
#define NB    9216            // histogram bins over score float bits >> 12
#define BASE_BIN 251084       // bits(0.05f) >> 12
#define SEL_CAP 1024
#define TPB   1024
#define DETS  100
#define CLIPV 4.135166556742356f   // log(1000/16)
#define FULLM 0xffffffffu

// ------------------------------------------------------------------
// static device scratch (zero-initialized at load; k_nms restores the
// zeros it consumed -> graph-replay deterministic)
// ------------------------------------------------------------------
__device__ unsigned long long g_keys[Bn][CAPc];
__device__ int                g_cnt [Bn];

__device__ __forceinline__ void stf(float* o, int i, float v, int n) {
    if (i < n) o[i] = v;
}

// reference-rounding IoU on offset coordinates; returns (iou > 0.5)
__device__ __forceinline__ bool iou_sup(float4 A, float4 Bx, float off) {
    float ax1 = A.x + off, ay1 = A.y + off, ax2 = A.z + off, ay2 = A.w + off;
    float bx1 = Bx.x + off, by1 = Bx.y + off, bx2 = Bx.z + off, by2 = Bx.w + off;
    float ltx = fmaxf(ax1, bx1), lty = fmaxf(ay1, by1);
    float rbx = fminf(ax2, bx2), rby = fminf(ay2, by2);
    float ww = fmaxf(rbx - ltx, 0.f), hh = fmaxf(rby - lty, 0.f);
    float inter = ww * hh;
    float a1 = (ax2 - ax1) * (ay2 - ay1);
    float a2 = (bx2 - bx1) * (by2 - by1);
    float iou = __fdiv_rn(inter, a1 + a2 - inter + 1e-9f);
    return iou > 0.5f;
}

// byte-identical box decode for candidate (g, c)
__device__ __forceinline__ float4 decode_box(const float* __restrict__ reg,
                                             const float* __restrict__ props,
                                             int g, int c) {
    float4 p = reinterpret_cast<const float4*>(props)[g];
    float w  = p.z - p.x;
    float h  = p.w - p.y;
    float cx = p.x + 0.5f * w;
    float cy = p.y + 0.5f * h;
    const float4* Q = reinterpret_cast<const float4*>(reg + (size_t)g * (Cn * 4));
    float4 q = Q[c];
    float dx = __fdiv_rn(q.x, 10.0f);
    float dy = __fdiv_rn(q.y, 10.0f);
    float dw = fminf(__fdiv_rn(q.z, 5.0f), CLIPV);
    float dh = fminf(__fdiv_rn(q.w, 5.0f), CLIPV);
    float pcx = dx * w + cx;
    float pcy = dy * h + cy;
    float pw  = expf(dw) * w;
    float ph  = expf(dh) * h;
    float x1 = fminf(fmaxf(pcx - 0.5f * pw, 0.f), 800.f);
    float y1 = fminf(fmaxf(pcy - 0.5f * ph, 0.f), 800.f);
    float x2 = fminf(fmaxf(pcx + 0.5f * pw, 0.f), 800.f);
    float y2 = fminf(fmaxf(pcy + 0.5f * ph, 0.f), 800.f);
    return make_float4(x1, y1, x2, y2);
}

// decode + filter + key emit for one proposal's survivors (warp-wide)
__device__ __forceinline__ void emit_prop(int g, int lane,
                                          unsigned mA, unsigned mB, unsigned mC,
                                          float e0, float e1, float e2, float s,
                                          const float* __restrict__ reg,
                                          const float* __restrict__ props,
                                          bool& ok, float& sc, int& c) {
    int c0  = __popc(mA);
    int c01 = c0 + __popc(mB);
    int tot = c01 + __popc(mC);
    ok = false; sc = 0.f; c = 0;
    if (tot == 0) return;

    int src = 0, k = 0;
    if (lane < c0)       { k = 0; src = __fns(mA, 0, lane + 1); }
    else if (lane < c01) { k = 1; src = __fns(mB, 0, lane - c0 + 1); }
    else if (lane < tot) { k = 2; src = __fns(mC, 0, lane - c01 + 1); }
    src &= 31;
    float eA = __shfl_sync(FULLM, e0, src);
    float eB = __shfl_sync(FULLM, e1, src);
    float eC = __shfl_sync(FULLM, e2, src);
    float e  = (k == 2) ? eC : ((k == 1) ? eB : eA);
    c = src + (k << 5);

    ok = (lane < tot);
    sc = __fdiv_rn(e, s);                 // exact softmax value
    ok = ok && (sc > 0.05f);
    if (ok) {
        float4 bx = decode_box(reg, props, g, c);
        ok = ((bx.z - bx.x) >= 1.0f) && ((bx.w - bx.y) >= 1.0f);
    }
}

// ------------------------------------------------------------------
// K1: four proposals per warp, interleaved chains
// ------------------------------------------------------------------
__global__ __launch_bounds__(256) void k_cand(const float* __restrict__ logits,
                                              const float* __restrict__ reg,
                                              const float* __restrict__ props) {
    int warp = threadIdx.x >> 5;
    int lane = threadIdx.x & 31;
    int g0 = blockIdx.x * 32 + warp * 4;      // 4 proposals, same image
    int b  = g0 >> 13;

    float l0[4], l1[4], l2[4], mx[4];
    #pragma unroll
    for (int p = 0; p < 4; p++) {
        const float* L = logits + (size_t)(g0 + p) * Cn;
        l0[p] = L[lane];
        l1[p] = (lane + 32 < Cn) ? L[lane + 32] : -1e30f;
        l2[p] = (lane + 64 < Cn) ? L[lane + 64] : -1e30f;
    }
    #pragma unroll
    for (int p = 0; p < 4; p++) mx[p] = fmaxf(l0[p], fmaxf(l1[p], l2[p]));
    #pragma unroll
    for (int o = 16; o; o >>= 1) {
        #pragma unroll
        for (int p = 0; p < 4; p++)
            mx[p] = fmaxf(mx[p], __shfl_xor_sync(FULLM, mx[p], o));
    }

    float e0[4], e1[4], e2[4], sden[4];
    #pragma unroll
    for (int p = 0; p < 4; p++) {
        e0[p] = expf(l0[p] - mx[p]);
        e1[p] = (lane + 32 < Cn) ? expf(l1[p] - mx[p]) : 0.0f;
        e2[p] = (lane + 64 < Cn) ? expf(l2[p] - mx[p]) : 0.0f;
        sden[p] = e0[p] + e1[p] + e2[p];
    }
    #pragma unroll
    for (int o = 16; o; o >>= 1) {
        #pragma unroll
        for (int p = 0; p < 4; p++)
            sden[p] += __shfl_xor_sync(FULLM, sden[p], o);
    }

    unsigned mA[4], mB[4], mC[4];
    unsigned anym = 0;
    #pragma unroll
    for (int p = 0; p < 4; p++) {
        float pt = 0.0497f * sden[p];   // conservative prefilter (>> 1ulp margin)
        mA[p] = __ballot_sync(FULLM, (lane >= 1) && (e0[p] > pt));
        mB[p] = __ballot_sync(FULLM, e1[p] > pt);
        mC[p] = __ballot_sync(FULLM, e2[p] > pt);
        anym |= mA[p] | mB[p] | mC[p];
    }
    if (anym == 0u) return;                   // warp-uniform

    bool ok[4]; float sc[4]; int cc[4];
    #pragma unroll
    for (int p = 0; p < 4; p++)
        emit_prop(g0 + p, lane, mA[p], mB[p], mC[p],
                  e0[p], e1[p], e2[p], sden[p], reg, props,
                  ok[p], sc[p], cc[p]);

    unsigned fm[4]; int pc[4];
    int tot = 0;
    #pragma unroll
    for (int p = 0; p < 4; p++) {
        fm[p] = __ballot_sync(FULLM, ok[p]);
        pc[p] = __popc(fm[p]);
        tot += pc[p];
    }
    if (tot) {
        int base = 0;
        if (lane == 0) base = atomicAdd(&g_cnt[b], tot);
        base = __shfl_sync(FULLM, base, 0);
        unsigned below = (1u << lane) - 1u;
        int off = base;
        #pragma unroll
        for (int p = 0; p < 4; p++) {
            if (ok[p]) {
                int pos = off + __popc(fm[p] & below);
                if (pos < CAPc) {
                    int n = (g0 + p) & (Nn - 1);
                    unsigned m = (unsigned)(n * 90 + (cc[p] - 1));
                    unsigned sbb = __float_as_uint(sc[p]);
                    g_keys[b][pos] = ((unsigned long long)sbb << 32) | (0xFFFFFFFFu - m);
                }
            }
            off += pc[p];
        }
    }
}

// ------------------------------------------------------------------
// K2 shared memory
// ------------------------------------------------------------------
struct SM {
    float4 sbox[SEL_CAP];               // window boxes (sorted order)
    float4 cls_acc[32][DETS];           // per-warp class accepted scratch
    float4 abox[DETS];                  // global accepted boxes
    unsigned long long skey[SEL_CAP];
    unsigned long long skey2[SEL_CAP];  // double buffer for bitonic stages
    int    slbl[SEL_CAP];
    int    sfx[NB];
    int    chunkcnt[32][128];           // per-(chunk,warp) class counts / bases
    int    cls_rank[SEL_CAP];
    int    cls_list[SEL_CAP];
    int    sflag[SEL_CAP];
    int    cls_cnt[128];
    int    cls_off[96];
    int    albl[DETS];
    int    wtot[32], wexc[32], wsum[32];
    int    s_cnt, s_acc, s_surv;
};

__global__ __launch_bounds__(TPB) void k_nms(const float* __restrict__ reg,
                                             const float* __restrict__ props,
                                             float* __restrict__ out, int out_size) {
    extern __shared__ __align__(16) char smraw[];
    SM* sm = reinterpret_cast<SM*>(smraw);
    int b = blockIdx.x;
    int t = threadIdx.x;
    int lane = t & 31;
    int warp = t >> 5;

    int Ktot = min(g_cnt[b], CAPc);

    // ---- build histogram in smem from keys (MLP-8 batched) ----
    const int PER = NB / TPB;   // 9
    int lo = t * PER;
    #pragma unroll
    for (int i = 0; i < PER; i++) sm->sfx[lo + i] = 0;
    __syncthreads();
    for (int i0 = 0; i0 < Ktot; i0 += TPB * 8) {
        unsigned long long kv[8];
        #pragma unroll
        for (int k = 0; k < 8; k++) {
            int i = i0 + k * TPB + t;
            kv[k] = (i < Ktot) ? g_keys[b][i] : 0ULL;
        }
        #pragma unroll
        for (int k = 0; k < 8; k++) {
            if (kv[k]) {
                int bin = (int)((unsigned)(kv[k] >> 32) >> 12) - BASE_BIN;
                bin = max(0, min(bin, NB - 1));
                atomicAdd(&sm->sfx[bin], 1);
            }
        }
    }
    __syncthreads();

    // ---- hierarchical suffix sums in place ----
    int cnts[PER];
    #pragma unroll
    for (int i = 0; i < PER; i++) cnts[i] = sm->sfx[lo + i];
    int ls = 0;
    #pragma unroll
    for (int i = 0; i < PER; i++) ls += cnts[i];
    int v = ls;
    #pragma unroll
    for (int off = 1; off < 32; off <<= 1) {
        int u = __shfl_down_sync(FULLM, v, off);
        if (lane + off < 32) v += u;
    }
    if (lane == 0) sm->wtot[warp] = v;
    __syncthreads();
    if (t < 32) {
        int x = sm->wtot[t];
        int vv = x;
        #pragma unroll
        for (int off = 1; off < 32; off <<= 1) {
            int u = __shfl_down_sync(FULLM, vv, off);
            if (t + off < 32) vv += u;
        }
        sm->wexc[t] = vv - x;
    }
    if (t == 0) sm->s_acc = 0;
    __syncthreads();
    int run = sm->wexc[warp] + (v - ls);
    for (int i = PER - 1; i >= 0; i--) {
        run += cnts[i];
        sm->sfx[lo + i] = run;
    }
    __syncthreads();

    int b_hi = NB;

    while (sm->s_acc < DETS) {
        int top = (b_hi < NB) ? sm->sfx[b_hi] : 0;
        if (b_hi == 0 || sm->sfx[0] - top == 0) break;

        // smallest wlo with sfx[wlo] - top <= SEL_CAP
        int sl = 0, sh = b_hi;
        while (sl < sh) {
            int mid = (sl + sh) >> 1;
            if (sm->sfx[mid] - top <= SEL_CAP) sh = mid; else sl = mid + 1;
        }
        int wlo = sl;
        if (wlo >= b_hi) wlo = b_hi - 1;
        int whi = b_hi;
        b_hi = wlo;

        if (t == 0) sm->s_cnt = 0;
        __syncthreads();
        // ---- MLP-8 selection scan ----
        for (int i0 = 0; i0 < Ktot; i0 += TPB * 8) {
            unsigned long long kv[8];
            #pragma unroll
            for (int k = 0; k < 8; k++) {
                int i = i0 + k * TPB + t;
                kv[k] = (i < Ktot) ? g_keys[b][i] : 0ULL;
            }
            #pragma unroll
            for (int k = 0; k < 8; k++) {
                if (kv[k]) {
                    int bin = (int)((unsigned)(kv[k] >> 32) >> 12) - BASE_BIN;
                    bin = max(0, min(bin, NB - 1));
                    if (bin >= wlo && bin < whi) {
                        int pos = atomicAdd(&sm->s_cnt, 1);
                        if (pos < SEL_CAP) sm->skey[pos] = kv[k];
                    }
                }
            }
        }
        __syncthreads();
        int nsel = min(sm->s_cnt, SEL_CAP);
        if (nsel == 0) continue;

        {
            int i = nsel + t;
            if (i < SEL_CAP) sm->skey[i] = 0ULL;
        }
        __syncthreads();

        // ---- register+shfl bitonic sort, descending, P=1024 ----
        // double-buffered smem stages: ONE barrier per exchange stage
        {
            unsigned long long key = sm->skey[t];
            int useB = 1;
            #pragma unroll
            for (int k2 = 2; k2 <= SEL_CAP; k2 <<= 1) {
                for (int j = k2 >> 1; j > 0; j >>= 1) {
                    unsigned long long partner;
                    if (j >= 32) {
                        unsigned long long* W = useB ? sm->skey2 : sm->skey;
                        W[t] = key;
                        __syncthreads();
                        partner = W[t ^ j];
                        useB ^= 1;
                    } else {
                        partner = __shfl_xor_sync(FULLM, key, j);
                    }
                    bool desc    = ((t & k2) == 0);
                    bool lowerIx = ((t & j) == 0);
                    bool takeMax = (desc == lowerIx);
                    bool pG      = (partner > key);
                    if (takeMax == pG) key = partner;
                }
            }
            __syncthreads();
            sm->skey[t] = key;
            __syncthreads();
        }

        // ---- decode boxes + labels in sorted order; reset counters ----
        int mylbl;
        if (t < nsel) {
            unsigned m = 0xFFFFFFFFu - (unsigned)sm->skey[t];
            int n = (int)(m / 90u);
            int c = (int)(m % 90u) + 1;
            sm->sbox[t] = decode_box(reg, props, b * Nn + n, c);
            sm->slbl[t] = c;
            mylbl = c;
        } else {
            mylbl = 96 + lane;            // unique-per-lane pad label
        }
        sm->sflag[t] = 0;
        {
            #pragma unroll
            for (int i = 0; i < 4; i++) sm->chunkcnt[(t * 4 + i) >> 7][(t * 4 + i) & 127] = 0;
        }
        __syncthreads();

        // ---- parallel per-chunk ranks: warp w handles items w*32+lane ----
        unsigned peers = __match_any_sync(FULLM, mylbl);
        int lrank = __popc(peers & ((1u << lane) - 1u));
        int leader = __ffs(peers) - 1;
        if (lane == leader) sm->chunkcnt[warp][mylbl] = __popc(peers);
        __syncthreads();

        // ---- per-class prefix across the 32 chunks (128 threads) ----
        if (t < 128) {
            int run2 = 0;
            #pragma unroll 1
            for (int w = 0; w < 32; w++) {
                int tmp = sm->chunkcnt[w][t];
                sm->chunkcnt[w][t] = run2;   // becomes chunk base
                run2 += tmp;
            }
            sm->cls_cnt[t] = run2;
        }
        __syncthreads();

        if (t < nsel) sm->cls_rank[t] = sm->chunkcnt[warp][mylbl] + lrank;
        __syncthreads();

        // ---- exclusive offsets over classes 0..95 ----
        if (t < 32) {
            int c0i = t * 3;
            int s0 = sm->cls_cnt[c0i], s1 = sm->cls_cnt[c0i + 1], s2 = sm->cls_cnt[c0i + 2];
            int tt = s0 + s1 + s2;
            int rn = tt;
            #pragma unroll
            for (int off = 1; off < 32; off <<= 1) {
                int u = __shfl_up_sync(FULLM, rn, off);
                if (lane >= off) rn += u;
            }
            int ex = rn - tt;
            sm->cls_off[c0i] = ex;
            sm->cls_off[c0i + 1] = ex + s0;
            sm->cls_off[c0i + 2] = ex + s0 + s1;
        }
        __syncthreads();

        // ---- scatter per-class lists (stable: score order within class) --
        if (t < nsel) sm->cls_list[sm->cls_off[mylbl] + sm->cls_rank[t]] = t;
        int acc0 = sm->s_acc;
        int quota = DETS - acc0;
        __syncthreads();

        // ---- per-class greedy: warp w handles classes w+1, w+33, w+65 ----
        #pragma unroll
        for (int jc = 0; jc < 3; jc++) {
            int c = warp + 1 + 32 * jc;
            if (c > 90) continue;
            int cnt = sm->cls_cnt[c];
            if (cnt == 0) continue;
            int off = sm->cls_off[c];
            float offv = (float)c * 801.0f;

            int nacc = 0;
            for (int a0 = 0; a0 < acc0; a0 += 32) {
                int a = a0 + lane;
                bool mth = (a < acc0) && (sm->albl[a] == c);
                unsigned mm = __ballot_sync(FULLM, mth);
                if (mth) sm->cls_acc[warp][nacc + __popc(mm & ((1u << lane) - 1u))] = sm->abox[a];
                nacc += __popc(mm);
            }

            int newacc = 0;
            for (int j = 0; j < cnt; j++) {
                int i = sm->cls_list[off + j];
                float4 bx = sm->sbox[i];
                bool sup = false;
                for (int a = lane; a < nacc; a += 32)
                    sup |= iou_sup(sm->cls_acc[warp][a], bx, offv);
                if (!__any_sync(FULLM, sup)) {
                    if (lane == 0) {
                        sm->sflag[i] = 1;
                        sm->cls_acc[warp][nacc] = bx;
                    }
                    nacc++;
                    newacc++;
                    if (newacc >= quota) break;
                }
            }
        }
        __syncthreads();

        // ---- prefix over survivor flags; output first quota in order ----
        {
            int f = sm->sflag[t];
            int scn = f;
            #pragma unroll
            for (int off = 1; off < 32; off <<= 1) {
                int u = __shfl_up_sync(FULLM, scn, off);
                if (lane >= off) scn += u;
            }
            if (lane == 31) sm->wsum[warp] = scn;
            __syncthreads();
            if (t < 32) {
                int x = sm->wsum[t];
                int s2 = x;
                #pragma unroll
                for (int off = 1; off < 32; off <<= 1) {
                    int u = __shfl_up_sync(FULLM, s2, off);
                    if (t >= off) s2 += u;
                }
                sm->wsum[t] = s2 - x;
            }
            __syncthreads();
            int incl = scn + sm->wsum[warp];
            int r = incl - f;
            if (f && (acc0 + r) < DETS) {
                int slot = acc0 + r;
                float4 bx = sm->sbox[t];
                int lbl = sm->slbl[t];
                sm->abox[slot] = bx;
                sm->albl[slot] = lbl;
                float sc = __uint_as_float((unsigned)(sm->skey[t] >> 32));
                stf(out, b * (DETS * 4) + slot * 4 + 0, bx.x, out_size);
                stf(out, b * (DETS * 4) + slot * 4 + 1, bx.y, out_size);
                stf(out, b * (DETS * 4) + slot * 4 + 2, bx.z, out_size);
                stf(out, b * (DETS * 4) + slot * 4 + 3, bx.w, out_size);
                stf(out, Bn * DETS * 4 + b * DETS + slot, sc, out_size);
                stf(out, Bn * DETS * 5 + b * DETS + slot, (float)lbl, out_size);
                stf(out, Bn * DETS * 6 + b * DETS + slot, 1.0f, out_size);
            }
            if (t == TPB - 1) sm->s_surv = incl;
            __syncthreads();
            if (t == 0) sm->s_acc = min(acc0 + sm->s_surv, DETS);
            __syncthreads();
        }
    }

    // ---- zero-fill remaining detection slots ----
    __syncthreads();
    int accF = sm->s_acc;
    for (int a = accF + t; a < DETS; a += TPB) {
        stf(out, b * (DETS * 4) + a * 4 + 0, 0.f, out_size);
        stf(out, b * (DETS * 4) + a * 4 + 1, 0.f, out_size);
        stf(out, b * (DETS * 4) + a * 4 + 2, 0.f, out_size);
        stf(out, b * (DETS * 4) + a * 4 + 3, 0.f, out_size);
        stf(out, Bn * DETS * 4 + b * DETS + a, 0.f, out_size);
        stf(out, Bn * DETS * 5 + b * DETS + a, 0.f, out_size);
        stf(out, Bn * DETS * 6 + b * DETS + a, 0.f, out_size);
    }

    // ---- restore zeros for next graph replay ----
    if (t == 0) g_cnt[b] = 0;
}

// ------------------------------------------------------------------
// launcher
// ------------------------------------------------------------------
extern "C" void kernel_launch(void* const* d_in, const int* in_sizes, int n_in,
                              void* d_out, int out_size) {
    const float* logits = nullptr;
    const float* reg    = nullptr;
    const float* props  = nullptr;
    for (int i = 0; i < n_in; i++) {
        if      (in_sizes[i] == Bn * Nn * Cn)     logits = (const float*)d_in[i];
        else if (in_sizes[i] == Bn * Nn * Cn * 4) reg    = (const float*)d_in[i];
        else if (in_sizes[i] == Bn * Nn * 4)      props  = (const float*)d_in[i];
    }
    if (!logits && n_in > 0) logits = (const float*)d_in[0];
    if (!reg    && n_in > 1) reg    = (const float*)d_in[1];
    if (!props  && n_in > 2) props  = (const float*)d_in[2];

    cudaFuncSetAttribute(k_nms, cudaFuncAttributeMaxDynamicSharedMemorySize,
                         (int)sizeof(SM));

    k_cand<<<(Bn * Nn) / 32, 256>>>(logits, reg, props);
    k_nms<<<Bn, TPB, sizeof(SM)>>>(reg, props, (float*)d_out, out_size);
}

// round 15
// speedup vs baseline: 1.9776x; 1.1948x over previous
#include <cuda_runtime.h>
#include <cstdint>

#define Bn    8
#define Nn    8192
#define Cn    91
#define CAPc  163840          // >= max kept candidates per image
#define NB    9216            // histogram bins over score float bits >> 12
#define BASE_BIN 251084       // bits(0.05f) >> 12
#define SEL_CAP 1024
#define TPB   1024
#define DETS  100
#define CLIPV 4.135166556742356f   // log(1000/16)
#define FULLM 0xffffffffu

// ------------------------------------------------------------------
// static device scratch (zero-initialized at load; k_nms restores the
// zeros it consumed -> graph-replay deterministic)
// ------------------------------------------------------------------
__device__ unsigned long long g_keys[Bn][CAPc];
__device__ int                g_cnt [Bn];
__device__ int                g_hist[Bn][NB];

__device__ __forceinline__ void stf(float* o, int i, float v, int n) {
    if (i < n) o[i] = v;
}

// reference-rounding IoU on offset coordinates; returns (iou > 0.5)
__device__ __forceinline__ bool iou_sup(float4 A, float4 Bx, float off) {
    float ax1 = A.x + off, ay1 = A.y + off, ax2 = A.z + off, ay2 = A.w + off;
    float bx1 = Bx.x + off, by1 = Bx.y + off, bx2 = Bx.z + off, by2 = Bx.w + off;
    float ltx = fmaxf(ax1, bx1), lty = fmaxf(ay1, by1);
    float rbx = fminf(ax2, bx2), rby = fminf(ay2, by2);
    float ww = fmaxf(rbx - ltx, 0.f), hh = fmaxf(rby - lty, 0.f);
    float inter = ww * hh;
    float a1 = (ax2 - ax1) * (ay2 - ay1);
    float a2 = (bx2 - bx1) * (by2 - by1);
    float iou = __fdiv_rn(inter, a1 + a2 - inter + 1e-9f);
    return iou > 0.5f;
}

// byte-identical box decode for candidate (g, c)
__device__ __forceinline__ float4 decode_box(const float* __restrict__ reg,
                                             const float* __restrict__ props,
                                             int g, int c) {
    float4 p = reinterpret_cast<const float4*>(props)[g];
    float w  = p.z - p.x;
    float h  = p.w - p.y;
    float cx = p.x + 0.5f * w;
    float cy = p.y + 0.5f * h;
    const float4* Q = reinterpret_cast<const float4*>(reg + (size_t)g * (Cn * 4));
    float4 q = Q[c];
    float dx = __fdiv_rn(q.x, 10.0f);
    float dy = __fdiv_rn(q.y, 10.0f);
    float dw = fminf(__fdiv_rn(q.z, 5.0f), CLIPV);
    float dh = fminf(__fdiv_rn(q.w, 5.0f), CLIPV);
    float pcx = dx * w + cx;
    float pcy = dy * h + cy;
    float pw  = expf(dw) * w;
    float ph  = expf(dh) * h;
    float x1 = fminf(fmaxf(pcx - 0.5f * pw, 0.f), 800.f);
    float y1 = fminf(fmaxf(pcy - 0.5f * ph, 0.f), 800.f);
    float x2 = fminf(fmaxf(pcx + 0.5f * pw, 0.f), 800.f);
    float y2 = fminf(fmaxf(pcy + 0.5f * ph, 0.f), 800.f);
    return make_float4(x1, y1, x2, y2);
}

// decode + filter + key emit for one proposal's survivors (warp-wide)
__device__ __forceinline__ void emit_prop(int g, int lane,
                                          unsigned mA, unsigned mB, unsigned mC,
                                          float e0, float e1, float e2, float s,
                                          const float* __restrict__ reg,
                                          const float* __restrict__ props,
                                          bool& ok, float& sc, int& c) {
    int c0  = __popc(mA);
    int c01 = c0 + __popc(mB);
    int tot = c01 + __popc(mC);
    ok = false; sc = 0.f; c = 0;
    if (tot == 0) return;

    int src = 0, k = 0;
    if (lane < c0)       { k = 0; src = __fns(mA, 0, lane + 1); }
    else if (lane < c01) { k = 1; src = __fns(mB, 0, lane - c0 + 1); }
    else if (lane < tot) { k = 2; src = __fns(mC, 0, lane - c01 + 1); }
    src &= 31;
    float eA = __shfl_sync(FULLM, e0, src);
    float eB = __shfl_sync(FULLM, e1, src);
    float eC = __shfl_sync(FULLM, e2, src);
    float e  = (k == 2) ? eC : ((k == 1) ? eB : eA);
    c = src + (k << 5);

    ok = (lane < tot);
    sc = __fdiv_rn(e, s);                 // exact softmax value
    ok = ok && (sc > 0.05f);
    if (ok) {
        float4 bx = decode_box(reg, props, g, c);
        ok = ((bx.z - bx.x) >= 1.0f) && ((bx.w - bx.y) >= 1.0f);
    }
}

// ------------------------------------------------------------------
// K1: four proposals per warp, interleaved chains + histogram
// ------------------------------------------------------------------
__global__ __launch_bounds__(256) void k_cand(const float* __restrict__ logits,
                                              const float* __restrict__ reg,
                                              const float* __restrict__ props) {
    int warp = threadIdx.x >> 5;
    int lane = threadIdx.x & 31;
    int g0 = blockIdx.x * 32 + warp * 4;      // 4 proposals, same image
    int b  = g0 >> 13;

    float l0[4], l1[4], l2[4], mx[4];
    #pragma unroll
    for (int p = 0; p < 4; p++) {
        const float* L = logits + (size_t)(g0 + p) * Cn;
        l0[p] = L[lane];
        l1[p] = (lane + 32 < Cn) ? L[lane + 32] : -1e30f;
        l2[p] = (lane + 64 < Cn) ? L[lane + 64] : -1e30f;
    }
    #pragma unroll
    for (int p = 0; p < 4; p++) mx[p] = fmaxf(l0[p], fmaxf(l1[p], l2[p]));
    #pragma unroll
    for (int o = 16; o; o >>= 1) {
        #pragma unroll
        for (int p = 0; p < 4; p++)
            mx[p] = fmaxf(mx[p], __shfl_xor_sync(FULLM, mx[p], o));
    }

    float e0[4], e1[4], e2[4], sden[4];
    #pragma unroll
    for (int p = 0; p < 4; p++) {
        e0[p] = expf(l0[p] - mx[p]);
        e1[p] = (lane + 32 < Cn) ? expf(l1[p] - mx[p]) : 0.0f;
        e2[p] = (lane + 64 < Cn) ? expf(l2[p] - mx[p]) : 0.0f;
        sden[p] = e0[p] + e1[p] + e2[p];
    }
    #pragma unroll
    for (int o = 16; o; o >>= 1) {
        #pragma unroll
        for (int p = 0; p < 4; p++)
            sden[p] += __shfl_xor_sync(FULLM, sden[p], o);
    }

    unsigned mA[4], mB[4], mC[4];
    unsigned anym = 0;
    #pragma unroll
    for (int p = 0; p < 4; p++) {
        float pt = 0.0497f * sden[p];   // conservative prefilter (>> 1ulp margin)
        mA[p] = __ballot_sync(FULLM, (lane >= 1) && (e0[p] > pt));
        mB[p] = __ballot_sync(FULLM, e1[p] > pt);
        mC[p] = __ballot_sync(FULLM, e2[p] > pt);
        anym |= mA[p] | mB[p] | mC[p];
    }
    if (anym == 0u) return;                   // warp-uniform

    bool ok[4]; float sc[4]; int cc[4];
    #pragma unroll
    for (int p = 0; p < 4; p++)
        emit_prop(g0 + p, lane, mA[p], mB[p], mC[p],
                  e0[p], e1[p], e2[p], sden[p], reg, props,
                  ok[p], sc[p], cc[p]);

    unsigned fm[4]; int pc[4];
    int tot = 0;
    #pragma unroll
    for (int p = 0; p < 4; p++) {
        fm[p] = __ballot_sync(FULLM, ok[p]);
        pc[p] = __popc(fm[p]);
        tot += pc[p];
    }
    if (tot) {
        int base = 0;
        if (lane == 0) base = atomicAdd(&g_cnt[b], tot);
        base = __shfl_sync(FULLM, base, 0);
        unsigned below = (1u << lane) - 1u;
        int off = base;
        #pragma unroll
        for (int p = 0; p < 4; p++) {
            if (ok[p]) {
                int pos = off + __popc(fm[p] & below);
                if (pos < CAPc) {
                    int n = (g0 + p) & (Nn - 1);
                    unsigned m = (unsigned)(n * 90 + (cc[p] - 1));
                    unsigned sbb = __float_as_uint(sc[p]);
                    g_keys[b][pos] = ((unsigned long long)sbb << 32) | (0xFFFFFFFFu - m);
                    int bin = (int)(sbb >> 12) - BASE_BIN;
                    bin = max(0, min(bin, NB - 1));
                    atomicAdd(&g_hist[b][bin], 1);
                }
            }
            off += pc[p];
        }
    }
}

// ------------------------------------------------------------------
// K2 shared memory
// ------------------------------------------------------------------
struct SM {
    float4 sbox[SEL_CAP];               // window boxes (sorted order)
    float4 cls_acc[32][DETS];           // fallback-path accepted scratch
    float4 abox[DETS];                  // global accepted boxes
    unsigned long long skey[SEL_CAP];
    unsigned long long skey2[SEL_CAP];  // double buffer for bitonic stages
    unsigned mask[SEL_CAP][4];          // per-rank suppression bitmask (<=128)
    int    slbl[SEL_CAP];
    int    sfx[NB];
    int    chunkcnt[32][128];           // per-(chunk,warp) class counts / bases
    int    cls_rank[SEL_CAP];
    int    cls_list[SEL_CAP];
    int    sflag[SEL_CAP];
    int    presup[SEL_CAP];
    int    cls_cnt[128];
    int    cls_off[96];
    int    albl[DETS];
    int    wtot[32], wexc[32], wsum[32];
    int    s_cnt, s_acc, s_surv;
};

__global__ __launch_bounds__(TPB) void k_nms(const float* __restrict__ reg,
                                             const float* __restrict__ props,
                                             float* __restrict__ out, int out_size) {
    extern __shared__ __align__(16) char smraw[];
    SM* sm = reinterpret_cast<SM*>(smraw);
    int b = blockIdx.x;
    int t = threadIdx.x;
    int lane = t & 31;
    int warp = t >> 5;

    int Ktot = min(g_cnt[b], CAPc);

    // ---- load histogram (built by k_cand) + restore zeros ----
    const int PER = NB / TPB;   // 9
    int lo = t * PER;
    int cnts[PER];
    #pragma unroll
    for (int i = 0; i < PER; i++) {
        cnts[i] = g_hist[b][lo + i];
        g_hist[b][lo + i] = 0;
    }

    // ---- hierarchical suffix sums ----
    int ls = 0;
    #pragma unroll
    for (int i = 0; i < PER; i++) ls += cnts[i];
    int v = ls;
    #pragma unroll
    for (int off = 1; off < 32; off <<= 1) {
        int u = __shfl_down_sync(FULLM, v, off);
        if (lane + off < 32) v += u;
    }
    if (lane == 0) sm->wtot[warp] = v;
    __syncthreads();
    if (t < 32) {
        int x = sm->wtot[t];
        int vv = x;
        #pragma unroll
        for (int off = 1; off < 32; off <<= 1) {
            int u = __shfl_down_sync(FULLM, vv, off);
            if (t + off < 32) vv += u;
        }
        sm->wexc[t] = vv - x;
    }
    if (t == 0) sm->s_acc = 0;
    __syncthreads();
    int run = sm->wexc[warp] + (v - ls);
    for (int i = PER - 1; i >= 0; i--) {
        run += cnts[i];
        sm->sfx[lo + i] = run;
    }
    __syncthreads();

    int b_hi = NB;

    while (sm->s_acc < DETS) {
        int top = (b_hi < NB) ? sm->sfx[b_hi] : 0;
        if (b_hi == 0 || sm->sfx[0] - top == 0) break;

        // smallest wlo with sfx[wlo] - top <= SEL_CAP
        int sl = 0, sh = b_hi;
        while (sl < sh) {
            int mid = (sl + sh) >> 1;
            if (sm->sfx[mid] - top <= SEL_CAP) sh = mid; else sl = mid + 1;
        }
        int wlo = sl;
        if (wlo >= b_hi) wlo = b_hi - 1;
        int whi = b_hi;
        b_hi = wlo;

        if (t == 0) sm->s_cnt = 0;
        __syncthreads();
        // ---- MLP-8 selection scan ----
        for (int i0 = 0; i0 < Ktot; i0 += TPB * 8) {
            unsigned long long kv[8];
            #pragma unroll
            for (int k = 0; k < 8; k++) {
                int i = i0 + k * TPB + t;
                kv[k] = (i < Ktot) ? g_keys[b][i] : 0ULL;
            }
            #pragma unroll
            for (int k = 0; k < 8; k++) {
                if (kv[k]) {
                    int bin = (int)((unsigned)(kv[k] >> 32) >> 12) - BASE_BIN;
                    bin = max(0, min(bin, NB - 1));
                    if (bin >= wlo && bin < whi) {
                        int pos = atomicAdd(&sm->s_cnt, 1);
                        if (pos < SEL_CAP) sm->skey[pos] = kv[k];
                    }
                }
            }
        }
        __syncthreads();
        int nsel = min(sm->s_cnt, SEL_CAP);
        if (nsel == 0) continue;

        {
            int i = nsel + t;
            if (i < SEL_CAP) sm->skey[i] = 0ULL;
        }
        __syncthreads();

        // ---- register+shfl bitonic sort, descending, P=1024 ----
        {
            unsigned long long key = sm->skey[t];
            int useB = 1;
            #pragma unroll
            for (int k2 = 2; k2 <= SEL_CAP; k2 <<= 1) {
                for (int j = k2 >> 1; j > 0; j >>= 1) {
                    unsigned long long partner;
                    if (j >= 32) {
                        unsigned long long* W = useB ? sm->skey2 : sm->skey;
                        W[t] = key;
                        __syncthreads();
                        partner = W[t ^ j];
                        useB ^= 1;
                    } else {
                        partner = __shfl_xor_sync(FULLM, key, j);
                    }
                    bool desc    = ((t & k2) == 0);
                    bool lowerIx = ((t & j) == 0);
                    bool takeMax = (desc == lowerIx);
                    bool pG      = (partner > key);
                    if (takeMax == pG) key = partner;
                }
            }
            __syncthreads();
            sm->skey[t] = key;
            __syncthreads();
        }

        // ---- decode boxes + labels in sorted order; reset counters ----
        int mylbl;
        if (t < nsel) {
            unsigned m = 0xFFFFFFFFu - (unsigned)sm->skey[t];
            int n = (int)(m / 90u);
            int c = (int)(m % 90u) + 1;
            sm->sbox[t] = decode_box(reg, props, b * Nn + n, c);
            sm->slbl[t] = c;
            mylbl = c;
        } else {
            mylbl = 96 + lane;            // unique-per-lane pad label
        }
        sm->sflag[t] = 0;
        {
            #pragma unroll
            for (int i = 0; i < 4; i++) sm->chunkcnt[(t * 4 + i) >> 7][(t * 4 + i) & 127] = 0;
        }
        __syncthreads();

        // ---- parallel per-chunk ranks: warp w handles items w*32+lane ----
        unsigned peers = __match_any_sync(FULLM, mylbl);
        int lrank = __popc(peers & ((1u << lane) - 1u));
        int leader = __ffs(peers) - 1;
        if (lane == leader) sm->chunkcnt[warp][mylbl] = __popc(peers);
        __syncthreads();

        // ---- per-class prefix across the 32 chunks (128 threads) ----
        if (t < 128) {
            int run2 = 0;
            #pragma unroll 1
            for (int w = 0; w < 32; w++) {
                int tmp = sm->chunkcnt[w][t];
                sm->chunkcnt[w][t] = run2;   // becomes chunk base
                run2 += tmp;
            }
            sm->cls_cnt[t] = run2;
        }
        __syncthreads();

        if (t < nsel) sm->cls_rank[t] = sm->chunkcnt[warp][mylbl] + lrank;
        __syncthreads();

        // ---- exclusive offsets over classes 0..95 ----
        if (t < 32) {
            int c0i = t * 3;
            int s0 = sm->cls_cnt[c0i], s1 = sm->cls_cnt[c0i + 1], s2 = sm->cls_cnt[c0i + 2];
            int tt = s0 + s1 + s2;
            int rn = tt;
            #pragma unroll
            for (int off = 1; off < 32; off <<= 1) {
                int u = __shfl_up_sync(FULLM, rn, off);
                if (lane >= off) rn += u;
            }
            int ex = rn - tt;
            sm->cls_off[c0i] = ex;
            sm->cls_off[c0i + 1] = ex + s0;
            sm->cls_off[c0i + 2] = ex + s0 + s1;
        }
        __syncthreads();

        // ---- scatter per-class lists (stable: score order within class) --
        if (t < nsel) sm->cls_list[sm->cls_off[mylbl] + sm->cls_rank[t]] = t;
        int acc0 = sm->s_acc;
        int quota = DETS - acc0;
        __syncthreads();

        // ---- phase A: presuppression by prior-round accepted boxes ----
        {
            int ps = 0;
            if (t < nsel && acc0 > 0) {
                float4 bi = sm->sbox[t];
                int li = mylbl;
                float offv = (float)li * 801.0f;
                for (int a = 0; a < acc0; a++) {
                    if (sm->albl[a] == li && iou_sup(sm->abox[a], bi, offv)) { ps = 1; break; }
                }
            }
            sm->presup[t] = ps;
        }

        // ---- phase B: parallel mask build (classes with cnt <= 128) ----
        if (t < nsel) {
            int c = mylbl;
            int cnt = sm->cls_cnt[c];
            if (cnt <= 128) {
                int off = sm->cls_off[c];
                int r = sm->cls_rank[t];
                float4 bi = sm->sbox[t];
                float offv = (float)c * 801.0f;
                unsigned w0 = 0, w1 = 0, w2 = 0, w3 = 0;
                for (int j = r + 1; j < cnt; j++) {
                    int widx = sm->cls_list[off + j];
                    if (iou_sup(bi, sm->sbox[widx], offv)) {
                        int wsel = j >> 5;
                        unsigned bit = 1u << (j & 31);
                        if      (wsel == 0) w0 |= bit;
                        else if (wsel == 1) w1 |= bit;
                        else if (wsel == 2) w2 |= bit;
                        else                w3 |= bit;
                    }
                }
                sm->mask[off + r][0] = w0;
                sm->mask[off + r][1] = w1;
                sm->mask[off + r][2] = w2;
                sm->mask[off + r][3] = w3;
            }
        }
        __syncthreads();

        // ---- phase C: 90 concurrent single-lane greedy word-walks ----
        if (t < 90) {
            int c = t + 1;
            int cnt = sm->cls_cnt[c];
            if (cnt > 0 && cnt <= 128) {
                int off = sm->cls_off[c];
                unsigned S0 = 0, S1 = 0, S2 = 0, S3 = 0;
                int newacc = 0;
                for (int j = 0; j < cnt; j++) {
                    int wsel = j >> 5;
                    unsigned bit = 1u << (j & 31);
                    unsigned Sw = (wsel == 0) ? S0 : (wsel == 1) ? S1 : (wsel == 2) ? S2 : S3;
                    int widx = sm->cls_list[off + j];
                    if (!(Sw & bit) && !sm->presup[widx]) {
                        sm->sflag[widx] = 1;
                        newacc++;
                        if (newacc >= quota) break;
                        S0 |= sm->mask[off + j][0];
                        S1 |= sm->mask[off + j][1];
                        S2 |= sm->mask[off + j][2];
                        S3 |= sm->mask[off + j][3];
                    }
                }
            }
        }

        // ---- fallback: classes with cnt > 128 use serial warp greedy ----
        #pragma unroll
        for (int jc = 0; jc < 3; jc++) {
            int c = warp + 1 + 32 * jc;
            if (c > 90) continue;
            int cnt = sm->cls_cnt[c];
            if (cnt <= 128) continue;       // handled by mask path
            int off = sm->cls_off[c];
            float offv = (float)c * 801.0f;

            int nacc = 0;
            for (int a0 = 0; a0 < acc0; a0 += 32) {
                int a = a0 + lane;
                bool mth = (a < acc0) && (sm->albl[a] == c);
                unsigned mm = __ballot_sync(FULLM, mth);
                if (mth) sm->cls_acc[warp][nacc + __popc(mm & ((1u << lane) - 1u))] = sm->abox[a];
                nacc += __popc(mm);
            }

            int newacc = 0;
            for (int j = 0; j < cnt; j++) {
                int i = sm->cls_list[off + j];
                float4 bx = sm->sbox[i];
                bool sup = false;
                for (int a = lane; a < nacc; a += 32)
                    sup |= iou_sup(sm->cls_acc[warp][a], bx, offv);
                if (!__any_sync(FULLM, sup)) {
                    if (lane == 0) {
                        sm->sflag[i] = 1;
                        sm->cls_acc[warp][nacc] = bx;
                    }
                    nacc++;
                    newacc++;
                    if (newacc >= quota) break;
                }
            }
        }
        __syncthreads();

        // ---- prefix over survivor flags; output first quota in order ----
        {
            int f = sm->sflag[t];
            int scn = f;
            #pragma unroll
            for (int off = 1; off < 32; off <<= 1) {
                int u = __shfl_up_sync(FULLM, scn, off);
                if (lane >= off) scn += u;
            }
            if (lane == 31) sm->wsum[warp] = scn;
            __syncthreads();
            if (t < 32) {
                int x = sm->wsum[t];
                int s2 = x;
                #pragma unroll
                for (int off = 1; off < 32; off <<= 1) {
                    int u = __shfl_up_sync(FULLM, s2, off);
                    if (t >= off) s2 += u;
                }
                sm->wsum[t] = s2 - x;
            }
            __syncthreads();
            int incl = scn + sm->wsum[warp];
            int r = incl - f;
            if (f && (acc0 + r) < DETS) {
                int slot = acc0 + r;
                float4 bx = sm->sbox[t];
                int lbl = sm->slbl[t];
                sm->abox[slot] = bx;
                sm->albl[slot] = lbl;
                float sc = __uint_as_float((unsigned)(sm->skey[t] >> 32));
                stf(out, b * (DETS * 4) + slot * 4 + 0, bx.x, out_size);
                stf(out, b * (DETS * 4) + slot * 4 + 1, bx.y, out_size);
                stf(out, b * (DETS * 4) + slot * 4 + 2, bx.z, out_size);
                stf(out, b * (DETS * 4) + slot * 4 + 3, bx.w, out_size);
                stf(out, Bn * DETS * 4 + b * DETS + slot, sc, out_size);
                stf(out, Bn * DETS * 5 + b * DETS + slot, (float)lbl, out_size);
                stf(out, Bn * DETS * 6 + b * DETS + slot, 1.0f, out_size);
            }
            if (t == TPB - 1) sm->s_surv = incl;
            __syncthreads();
            if (t == 0) sm->s_acc = min(acc0 + sm->s_surv, DETS);
            __syncthreads();
        }
    }

    // ---- zero-fill remaining detection slots ----
    __syncthreads();
    int accF = sm->s_acc;
    for (int a = accF + t; a < DETS; a += TPB) {
        stf(out, b * (DETS * 4) + a * 4 + 0, 0.f, out_size);
        stf(out, b * (DETS * 4) + a * 4 + 1, 0.f, out_size);
        stf(out, b * (DETS * 4) + a * 4 + 2, 0.f, out_size);
        stf(out, b * (DETS * 4) + a * 4 + 3, 0.f, out_size);
        stf(out, Bn * DETS * 4 + b * DETS + a, 0.f, out_size);
        stf(out, Bn * DETS * 5 + b * DETS + a, 0.f, out_size);
        stf(out, Bn * DETS * 6 + b * DETS + a, 0.f, out_size);
    }

    // ---- restore zeros for next graph replay ----
    if (t == 0) g_cnt[b] = 0;
}

// ------------------------------------------------------------------
// launcher
// ------------------------------------------------------------------
extern "C" void kernel_launch(void* const* d_in, const int* in_sizes, int n_in,
                              void* d_out, int out_size) {
    const float* logits = nullptr;
    const float* reg    = nullptr;
    const float* props  = nullptr;
    for (int i = 0; i < n_in; i++) {
        if      (in_sizes[i] == Bn * Nn * Cn)     logits = (const float*)d_in[i];
        else if (in_sizes[i] == Bn * Nn * Cn * 4) reg    = (const float*)d_in[i];
        else if (in_sizes[i] == Bn * Nn * 4)      props  = (const float*)d_in[i];
    }
    if (!logits && n_in > 0) logits = (const float*)d_in[0];
    if (!reg    && n_in > 1) reg    = (const float*)d_in[1];
    if (!props  && n_in > 2) props  = (const float*)d_in[2];

    cudaFuncSetAttribute(k_nms, cudaFuncAttributeMaxDynamicSharedMemorySize,
                         (int)sizeof(SM));

    k_cand<<<(Bn * Nn) / 32, 256>>>(logits, reg, props);
    k_nms<<<Bn, TPB, sizeof(SM)>>>(reg, props, (float*)d_out, out_size);
}